// round 6
// baseline (speedup 1.0000x reference)
#include <cuda_runtime.h>
#include <math.h>

typedef unsigned long long u64;

// ---------------- device scratch (no allocations allowed) ----------------
__device__ float g_Wt1 [128 * 260];   // e_W1^T padded 258->260
__device__ float g_Wt2 [128 * 128];   // e_W2^T
__device__ float g_Wtc [128 * 128];   // c_W1^T
__device__ float g_Wtn1[128 * 256];   // n_W1^T
__device__ float g_Wtn2[128 * 128];   // n_W2^T
__device__ float g_agg [25000 * 128]; // segment-sum of edge_feat
__device__ int   g_idx64;             // 1 if edge_index is int64

// ---------------- packed f32x2 helpers ----------------
__device__ __forceinline__ u64 pk2(float lo, float hi) {
    u64 r; asm("mov.b64 %0,{%1,%2};" : "=l"(r) : "f"(lo), "f"(hi)); return r;
}
__device__ __forceinline__ void upk2(u64 v, float& lo, float& hi) {
    asm("mov.b64 {%0,%1},%2;" : "=f"(lo), "=f"(hi) : "l"(v));
}
__device__ __forceinline__ u64 fma2(u64 a, u64 b, u64 c) {
    u64 d; asm("fma.rn.f32x2 %0,%1,%2,%3;" : "=l"(d) : "l"(a), "l"(b), "l"(c)); return d;
}
__device__ __forceinline__ u64 add2(u64 a, u64 b) {
    u64 d; asm("add.rn.f32x2 %0,%1,%2;" : "=l"(d) : "l"(a), "l"(b)); return d;
}
__device__ __forceinline__ u64 mul2(u64 a, u64 b) {
    u64 d; asm("mul.rn.f32x2 %0,%1,%2;" : "=l"(d) : "l"(a), "l"(b)); return d;
}

// ---------------- prep: weight transposes + int64 detection ----------------
__global__ void prep_kernel(const float* __restrict__ eW1, const float* __restrict__ eW2,
                            const float* __restrict__ cW1, const float* __restrict__ nW1,
                            const float* __restrict__ nW2, const unsigned* __restrict__ ei) {
    int i = blockIdx.x * blockDim.x + threadIdx.x;
    if (i == 0) {
        // int64 little-endian high words are all zero for indices < 2^31
        int f = 1;
        for (int t = 0; t < 64; t++) if (ei[2 * t + 1] != 0u) { f = 0; break; }
        g_idx64 = f;
    }
    if (i < 128 * 260) {
        int c = i / 260, k = i % 260;
        g_Wt1[i] = (k < 258) ? eW1[k * 128 + c] : 0.0f;
    }
    int j = i - 128 * 260;
    if (j >= 0 && j < 128 * 128) { int c = j / 128, k = j % 128; g_Wt2[j]  = eW2[k * 128 + c]; }
    j -= 128 * 128;
    if (j >= 0 && j < 128 * 128) { int c = j / 128, k = j % 128; g_Wtc[j]  = cW1[k * 128 + c]; }
    j -= 128 * 128;
    if (j >= 0 && j < 128 * 256) { int c = j / 256, k = j % 256; g_Wtn1[j] = nW1[k * 128 + c]; }
    j -= 128 * 256;
    if (j >= 0 && j < 128 * 128) { int c = j / 128, k = j % 128; g_Wtn2[j] = nW2[k * 128 + c]; }
}

// ---------------- init: zero agg, seed coord_out with coord ----------------
__global__ void init_kernel(const float* __restrict__ coord, float* __restrict__ coord_out, int N) {
    int i = blockIdx.x * blockDim.x + threadIdx.x;
    if (i < N * 128) g_agg[i] = 0.0f;
    if (i < N * 3)   coord_out[i] = coord[i];
}

// ---------------- pair GEMV: acc[pair][chan] += inp_pair * W ----------------
// sw: warp's shared tile, row stride 10 floats, s[k*10 + 2p + q] = inp[edge 2p+q][k]
// Wt: transposed weights, row c has wstride floats (k contiguous)
template <int K4>
__device__ __forceinline__ void gemm_pairs(const float* __restrict__ sw,
                                           const float* __restrict__ Wt,
                                           int wstride, int lane, u64 acc[4][4]) {
    const float4* w0p = (const float4*)(Wt + (size_t)(lane      ) * wstride);
    const float4* w1p = (const float4*)(Wt + (size_t)(lane + 32 ) * wstride);
    const float4* w2p = (const float4*)(Wt + (size_t)(lane + 64 ) * wstride);
    const float4* w3p = (const float4*)(Wt + (size_t)(lane + 96 ) * wstride);
    for (int k4 = 0; k4 < K4; k4++) {
        float4 w0 = __ldg(w0p + k4);
        float4 w1 = __ldg(w1p + k4);
        float4 w2 = __ldg(w2p + k4);
        float4 w3 = __ldg(w3p + k4);
        const float* a = sw + k4 * 40;
#pragma unroll
        for (int kk = 0; kk < 4; kk++) {
            float f0 = ((const float*)&w0)[kk];
            float f1 = ((const float*)&w1)[kk];
            float f2 = ((const float*)&w2)[kk];
            float f3 = ((const float*)&w3)[kk];
            u64 d0 = pk2(f0, f0), d1 = pk2(f1, f1), d2 = pk2(f2, f2), d3 = pk2(f3, f3);
            const u64* av = (const u64*)(a + kk * 10);
#pragma unroll
            for (int p = 0; p < 4; p++) {
                u64 x = av[p];
                acc[p][0] = fma2(x, d0, acc[p][0]);
                acc[p][1] = fma2(x, d1, acc[p][1]);
                acc[p][2] = fma2(x, d2, acc[p][2]);
                acc[p][3] = fma2(x, d3, acc[p][3]);
            }
        }
    }
}

// ---------------- LayerNorm + SiLU on packed pairs ----------------
__device__ __forceinline__ void ln_silu_pairs(u64 acc[4][4],
                                              const float* __restrict__ g,
                                              const float* __restrict__ be, int l) {
    float gv[4], bv[4];
#pragma unroll
    for (int j = 0; j < 4; j++) { gv[j] = __ldg(g + l + 32 * j); bv[j] = __ldg(be + l + 32 * j); }
#pragma unroll
    for (int p = 0; p < 4; p++) {
        u64 s1 = add2(add2(acc[p][0], acc[p][1]), add2(acc[p][2], acc[p][3]));
        u64 s2 = mul2(acc[p][0], acc[p][0]);
        s2 = fma2(acc[p][1], acc[p][1], s2);
        s2 = fma2(acc[p][2], acc[p][2], s2);
        s2 = fma2(acc[p][3], acc[p][3], s2);
#pragma unroll
        for (int o = 16; o > 0; o >>= 1) {
            s1 = add2(s1, __shfl_xor_sync(0xffffffffu, s1, o));
            s2 = add2(s2, __shfl_xor_sync(0xffffffffu, s2, o));
        }
        float m0, m1, q0, q1;
        upk2(s1, m0, m1); upk2(s2, q0, q1);
        const float inv = 1.0f / 128.0f;
        m0 *= inv; m1 *= inv;
        float v0 = q0 * inv - m0 * m0, v1 = q1 * inv - m1 * m1;
        float r0 = rsqrtf(v0 + 1e-5f), r1 = rsqrtf(v1 + 1e-5f);
#pragma unroll
        for (int j = 0; j < 4; j++) {
            float x0, x1; upk2(acc[p][j], x0, x1);
            x0 = (x0 - m0) * r0 * gv[j] + bv[j];
            x1 = (x1 - m1) * r1 * gv[j] + bv[j];
            x0 = x0 / (1.0f + __expf(-x0));
            x1 = x1 / (1.0f + __expf(-x1));
            acc[p][j] = pk2(x0, x1);
        }
    }
}

__device__ __forceinline__ void init_bias(u64 acc[4][4], const float* __restrict__ b, int l) {
#pragma unroll
    for (int j = 0; j < 4; j++) {
        float bb = __ldg(b + l + 32 * j);
        u64 v = pk2(bb, bb);
        acc[0][j] = v; acc[1][j] = v; acc[2][j] = v; acc[3][j] = v;
    }
}

__device__ __forceinline__ void store_pairs(float* __restrict__ sw, u64 acc[4][4], int l) {
#pragma unroll
    for (int j = 0; j < 4; j++) {
        int c = l + 32 * j;
        u64* d = (u64*)(sw + c * 10);
        d[0] = acc[0][j]; d[1] = acc[1][j]; d[2] = acc[2][j]; d[3] = acc[3][j];
    }
}

// ---------------- edge kernel: 64 edges / block, 8 warps x 8 edges ----------------
__global__ __launch_bounds__(256, 2)
void edge_kernel(const float* __restrict__ h, const void* __restrict__ ei,
                 const float* __restrict__ coord, const float* __restrict__ eattr,
                 const float* __restrict__ e_b1, const float* __restrict__ e_g1, const float* __restrict__ e_be1,
                 const float* __restrict__ e_b2, const float* __restrict__ e_g2, const float* __restrict__ e_be2,
                 const float* __restrict__ c_b1, const float* __restrict__ c_g1, const float* __restrict__ c_be1,
                 const float* __restrict__ cW2,
                 float* __restrict__ coord_out, int E) {
    extern __shared__ float smem[];
    int w = threadIdx.x >> 5, l = threadIdx.x & 31;
    float* sw    = smem + w * 2600;
    int*   s_row = (int*)&smem[20800];
    int*   s_col = s_row + 64;
    float* s_cd  = (float*)(s_col + 64);
    int base = blockIdx.x * 64 + w * 8;

    if (l < 8) {
        int e = base + l;
        bool v = e < E;
        int ec = v ? e : 0;
        int r, c;
        if (g_idx64) {
            const long long* q = (const long long*)ei;
            r = (int)q[ec]; c = (int)q[(size_t)E + ec];
        } else {
            const int* q = (const int*)ei;
            r = q[ec]; c = q[E + ec];
        }
        float dx = coord[r * 3 + 0] - coord[c * 3 + 0];
        float dy = coord[r * 3 + 1] - coord[c * 3 + 1];
        float dz = coord[r * 3 + 2] - coord[c * 3 + 2];
        float radial = dx * dx + dy * dy + dz * dz;
        float invn = 1.0f / (sqrtf(radial + 1e-8f) + 1.0f);
        int p = l >> 1, qq = l & 1;
        sw[2560 + 2 * p + qq] = radial;      // k = 256
        sw[2570 + 2 * p + qq] = eattr[ec];   // k = 257
        s_row[w * 8 + l] = v ? r : -1;
        s_col[w * 8 + l] = c;
        s_cd[(w * 8 + l) * 3 + 0] = dx * invn;
        s_cd[(w * 8 + l) * 3 + 1] = dy * invn;
        s_cd[(w * 8 + l) * 3 + 2] = dz * invn;
    } else if (l < 16) {
        sw[2580 + (l - 8)] = 0.0f;           // k = 258 pad
    } else if (l < 24) {
        sw[2590 + (l - 16)] = 0.0f;          // k = 259 pad
    }
    __syncwarp();

    // gather h[row], h[col] into pair-interleaved tile
#pragma unroll
    for (int e = 0; e < 8; e++) {
        int r = s_row[w * 8 + e]; if (r < 0) r = 0;
        int c = s_col[w * 8 + e];
        int off = 2 * (e >> 1) + (e & 1);
#pragma unroll
        for (int m = 0; m < 4; m++) {
            int k = l + 32 * m;
            sw[k * 10 + off]         = __ldg(h + (size_t)r * 128 + k);
            sw[(128 + k) * 10 + off] = __ldg(h + (size_t)c * 128 + k);
        }
    }
    __syncwarp();

    u64 acc[4][4];

    // layer 1: [258] -> [128], LN, silu
    init_bias(acc, e_b1, l);
    gemm_pairs<65>(sw, g_Wt1, 260, l, acc);
    ln_silu_pairs(acc, e_g1, e_be1, l);
    store_pairs(sw, acc, l);
    __syncwarp();

    // layer 2: [128] -> [128], LN, silu -> edge_feat
    init_bias(acc, e_b2, l);
    gemm_pairs<32>(sw, g_Wt2, 128, l, acc);
    ln_silu_pairs(acc, e_g2, e_be2, l);

    // scatter edge_feat into agg
#pragma unroll
    for (int p = 0; p < 4; p++) {
        int r0 = s_row[w * 8 + 2 * p], r1 = s_row[w * 8 + 2 * p + 1];
#pragma unroll
        for (int j = 0; j < 4; j++) {
            float x0, x1; upk2(acc[p][j], x0, x1);
            int c = l + 32 * j;
            if (r0 >= 0) atomicAdd(&g_agg[(size_t)r0 * 128 + c], x0);
            if (r1 >= 0) atomicAdd(&g_agg[(size_t)r1 * 128 + c], x1);
        }
    }
    store_pairs(sw, acc, l);
    __syncwarp();

    // coord MLP: [128] -> [128], LN, silu, then dot with c_W2 -> cm
    init_bias(acc, c_b1, l);
    gemm_pairs<32>(sw, g_Wtc, 128, l, acc);
    ln_silu_pairs(acc, c_g1, c_be1, l);

    u64 cm[4];
#pragma unroll
    for (int p = 0; p < 4; p++) {
        u64 s = 0ull;
#pragma unroll
        for (int j = 0; j < 4; j++) {
            float wv = __ldg(cW2 + l + 32 * j);
            s = fma2(acc[p][j], pk2(wv, wv), s);
        }
#pragma unroll
        for (int o = 16; o > 0; o >>= 1)
            s = add2(s, __shfl_xor_sync(0xffffffffu, s, o));
        cm[p] = s;
    }
    if (l < 8) {
        float c0, c1; upk2(cm[l >> 1], c0, c1);
        float cmv = (l & 1) ? c1 : c0;
        int r = s_row[w * 8 + l];
        if (r >= 0) {
            atomicAdd(&coord_out[(size_t)r * 3 + 0], s_cd[(w * 8 + l) * 3 + 0] * cmv);
            atomicAdd(&coord_out[(size_t)r * 3 + 1], s_cd[(w * 8 + l) * 3 + 1] * cmv);
            atomicAdd(&coord_out[(size_t)r * 3 + 2], s_cd[(w * 8 + l) * 3 + 2] * cmv);
        }
    }
}

// ---------------- node kernel: 64 nodes / block ----------------
__global__ __launch_bounds__(256, 2)
void node_kernel(const float* __restrict__ h,
                 const float* __restrict__ n_b1, const float* __restrict__ n_g1,
                 const float* __restrict__ n_be1, const float* __restrict__ n_b2,
                 float* __restrict__ out, int N) {
    extern __shared__ float smem[];
    int w = threadIdx.x >> 5, l = threadIdx.x & 31;
    float* sw = smem + w * 2600;
    int base = blockIdx.x * 64 + w * 8;

#pragma unroll
    for (int e = 0; e < 8; e++) {
        int n = base + e;
        int nc = (n < N) ? n : 0;
        int off = 2 * (e >> 1) + (e & 1);
#pragma unroll
        for (int m = 0; m < 4; m++) {
            int k = l + 32 * m;
            sw[k * 10 + off]         = __ldg(h + (size_t)nc * 128 + k);
            sw[(128 + k) * 10 + off] = g_agg[(size_t)nc * 128 + k];
        }
    }
    __syncwarp();

    u64 acc[4][4];
    init_bias(acc, n_b1, l);
    gemm_pairs<64>(sw, g_Wtn1, 256, l, acc);
    ln_silu_pairs(acc, n_g1, n_be1, l);
    store_pairs(sw, acc, l);
    __syncwarp();

    init_bias(acc, n_b2, l);
    gemm_pairs<32>(sw, g_Wtn2, 128, l, acc);

#pragma unroll
    for (int p = 0; p < 4; p++) {
        int n0 = base + 2 * p, n1 = n0 + 1;
#pragma unroll
        for (int j = 0; j < 4; j++) {
            float x0, x1; upk2(acc[p][j], x0, x1);
            int c = l + 32 * j;
            if (n0 < N) out[(size_t)n0 * 128 + c] = x0 + __ldg(h + (size_t)n0 * 128 + c);
            if (n1 < N) out[(size_t)n1 * 128 + c] = x1 + __ldg(h + (size_t)n1 * 128 + c);
        }
    }
}

// ---------------- launch ----------------
extern "C" void kernel_launch(void* const* d_in, const int* in_sizes, int n_in,
                              void* d_out, int out_size) {
    const float* h     = (const float*)d_in[0];
    const void*  ei    = d_in[1];
    const float* coord = (const float*)d_in[2];
    const float* eattr = (const float*)d_in[3];
    const float* eW1  = (const float*)d_in[4];
    const float* eb1  = (const float*)d_in[5];
    const float* eg1  = (const float*)d_in[6];
    const float* ebe1 = (const float*)d_in[7];
    const float* eW2  = (const float*)d_in[8];
    const float* eb2  = (const float*)d_in[9];
    const float* eg2  = (const float*)d_in[10];
    const float* ebe2 = (const float*)d_in[11];
    const float* nW1  = (const float*)d_in[12];
    const float* nb1  = (const float*)d_in[13];
    const float* ng1  = (const float*)d_in[14];
    const float* nbe1 = (const float*)d_in[15];
    const float* nW2  = (const float*)d_in[16];
    const float* nb2  = (const float*)d_in[17];
    const float* cW1  = (const float*)d_in[18];
    const float* cb1  = (const float*)d_in[19];
    const float* cg1  = (const float*)d_in[20];
    const float* cbe1 = (const float*)d_in[21];
    const float* cW2  = (const float*)d_in[22];

    int N = in_sizes[0] / 128;
    int E = in_sizes[1] / 2;

    float* out       = (float*)d_out;
    float* coord_out = out + (size_t)N * 128;

    const int SMEM = 21120 * 4;  // 84.5 KB
    cudaFuncSetAttribute(edge_kernel, cudaFuncAttributeMaxDynamicSharedMemorySize, SMEM);
    cudaFuncSetAttribute(node_kernel, cudaFuncAttributeMaxDynamicSharedMemorySize, SMEM);

    prep_kernel<<<(115200 + 255) / 256, 256>>>(eW1, eW2, cW1, nW1, nW2, (const unsigned*)ei);
    init_kernel<<<(N * 128 + 255) / 256, 256>>>(coord, coord_out, N);
    edge_kernel<<<(E + 63) / 64, 256, SMEM>>>(h, ei, coord, eattr,
                                              eb1, eg1, ebe1, eb2, eg2, ebe2,
                                              cb1, cg1, cbe1, cW2, coord_out, E);
    node_kernel<<<(N + 63) / 64, 256, SMEM>>>(h, nb1, ng1, nbe1, nb2, out, N);
}

// round 7
// speedup vs baseline: 1.9412x; 1.9412x over previous
#include <cuda_runtime.h>
#include <math.h>

typedef unsigned long long u64;

// ---------------- device scratch (no allocations allowed) ----------------
__device__ float g_agg[25000 * 128]; // segment-sum of edge_feat
__device__ int   g_idx64;            // 1 if edge_index is int64

// ---------------- packed f32x2 helpers ----------------
__device__ __forceinline__ u64 pk2(float lo, float hi) {
    u64 r; asm("mov.b64 %0,{%1,%2};" : "=l"(r) : "f"(lo), "f"(hi)); return r;
}
__device__ __forceinline__ void upk2(u64 v, float& lo, float& hi) {
    asm("mov.b64 {%0,%1},%2;" : "=f"(lo), "=f"(hi) : "l"(v));
}
__device__ __forceinline__ u64 fma2(u64 a, u64 b, u64 c) {
    u64 d; asm("fma.rn.f32x2 %0,%1,%2,%3;" : "=l"(d) : "l"(a), "l"(b), "l"(c)); return d;
}
__device__ __forceinline__ u64 add2(u64 a, u64 b) {
    u64 d; asm("add.rn.f32x2 %0,%1,%2;" : "=l"(d) : "l"(a), "l"(b)); return d;
}
__device__ __forceinline__ u64 mul2(u64 a, u64 b) {
    u64 d; asm("mul.rn.f32x2 %0,%1,%2;" : "=l"(d) : "l"(a), "l"(b)); return d;
}

// ---------------- init: idx detect, zero agg, seed coord_out ----------------
__global__ void init_kernel(const float* __restrict__ coord, float* __restrict__ coord_out,
                            const unsigned* __restrict__ ei, int N) {
    int i = blockIdx.x * blockDim.x + threadIdx.x;
    if (i == 0) {
        int f = 1;
        for (int t = 0; t < 64; t++) if (ei[2 * t + 1] != 0u) { f = 0; break; }
        g_idx64 = f;
    }
    if (i < N * 128) g_agg[i] = 0.0f;
    if (i < N * 3)   coord_out[i] = coord[i];
}

// ============ core warp-level GEMM: 16 edges (8 f32x2 pairs) x 128 ch ============
// sw tile: row k (stride 20 floats), cols 0..15 = edges (pairs adjacent).
// W row-major [K][128]; lane l owns channels l, l+32, l+64, l+96 (coalesced LDG).
template <int K>
__device__ __forceinline__ void gemm_k(const float* __restrict__ sw,
                                       const float* __restrict__ W,
                                       int l, u64 acc[8][4]) {
    const float* wb = W + l;
#pragma unroll 4
    for (int k = 0; k < K; k++) {
        const float* wr = wb + k * 128;
        float f0 = __ldg(wr);
        float f1 = __ldg(wr + 32);
        float f2 = __ldg(wr + 64);
        float f3 = __ldg(wr + 96);
        const float4* a = (const float4*)(sw + k * 20);
        float4 A0 = a[0], A1 = a[1], A2 = a[2], A3 = a[3];
        u64 x[8];
        x[0] = ((const u64*)&A0)[0]; x[1] = ((const u64*)&A0)[1];
        x[2] = ((const u64*)&A1)[0]; x[3] = ((const u64*)&A1)[1];
        x[4] = ((const u64*)&A2)[0]; x[5] = ((const u64*)&A2)[1];
        x[6] = ((const u64*)&A3)[0]; x[7] = ((const u64*)&A3)[1];
        u64 w0 = pk2(f0, f0), w1 = pk2(f1, f1), w2 = pk2(f2, f2), w3 = pk2(f3, f3);
#pragma unroll
        for (int p = 0; p < 8; p++) {
            acc[p][0] = fma2(x[p], w0, acc[p][0]);
            acc[p][1] = fma2(x[p], w1, acc[p][1]);
            acc[p][2] = fma2(x[p], w2, acc[p][2]);
            acc[p][3] = fma2(x[p], w3, acc[p][3]);
        }
    }
}

__device__ __forceinline__ void init_bias(u64 acc[8][4], const float* __restrict__ b, int l) {
#pragma unroll
    for (int j = 0; j < 4; j++) {
        float bb = __ldg(b + l + 32 * j);
        u64 v = pk2(bb, bb);
#pragma unroll
        for (int p = 0; p < 8; p++) acc[p][j] = v;
    }
}

__device__ __forceinline__ void ln_silu(u64 acc[8][4],
                                        const float* __restrict__ g,
                                        const float* __restrict__ be, int l) {
    float gv[4], bv[4];
#pragma unroll
    for (int j = 0; j < 4; j++) { gv[j] = __ldg(g + l + 32 * j); bv[j] = __ldg(be + l + 32 * j); }
#pragma unroll
    for (int p = 0; p < 8; p++) {
        u64 s1 = add2(add2(acc[p][0], acc[p][1]), add2(acc[p][2], acc[p][3]));
        u64 s2 = mul2(acc[p][0], acc[p][0]);
        s2 = fma2(acc[p][1], acc[p][1], s2);
        s2 = fma2(acc[p][2], acc[p][2], s2);
        s2 = fma2(acc[p][3], acc[p][3], s2);
#pragma unroll
        for (int o = 16; o > 0; o >>= 1) {
            s1 = add2(s1, __shfl_xor_sync(0xffffffffu, s1, o));
            s2 = add2(s2, __shfl_xor_sync(0xffffffffu, s2, o));
        }
        float m0, m1, q0, q1;
        upk2(s1, m0, m1); upk2(s2, q0, q1);
        const float inv = 1.0f / 128.0f;
        m0 *= inv; m1 *= inv;
        float v0 = q0 * inv - m0 * m0, v1 = q1 * inv - m1 * m1;
        float r0 = rsqrtf(v0 + 1e-5f), r1 = rsqrtf(v1 + 1e-5f);
#pragma unroll
        for (int j = 0; j < 4; j++) {
            float x0, x1; upk2(acc[p][j], x0, x1);
            x0 = (x0 - m0) * r0 * gv[j] + bv[j];
            x1 = (x1 - m1) * r1 * gv[j] + bv[j];
            x0 = x0 / (1.0f + __expf(-x0));
            x1 = x1 / (1.0f + __expf(-x1));
            acc[p][j] = pk2(x0, x1);
        }
    }
}

__device__ __forceinline__ void store_tile(float* __restrict__ sw, u64 acc[8][4], int l) {
#pragma unroll
    for (int j = 0; j < 4; j++) {
        int c = l + 32 * j;
        u64* d = (u64*)(sw + c * 20);
#pragma unroll
        for (int p = 0; p < 8; p++) d[p] = acc[p][j];
    }
}

// per-warp smem: tile 132 rows x 20 floats = 2640 floats; meta 128 floats
static const int TILE_F  = 2640;
static const int META_F  = 128;
static const int SMEM_B  = (4 * TILE_F + 4 * META_F) * 4;  // 44288 bytes

// ---------------- edge kernel: 64 edges / block, 4 warps x 16 edges ----------------
__global__ __launch_bounds__(128, 3)
void edge_kernel(const float* __restrict__ h, const void* __restrict__ ei,
                 const float* __restrict__ coord, const float* __restrict__ eattr,
                 const float* __restrict__ eW1,
                 const float* __restrict__ e_b1, const float* __restrict__ e_g1, const float* __restrict__ e_be1,
                 const float* __restrict__ eW2,
                 const float* __restrict__ e_b2, const float* __restrict__ e_g2, const float* __restrict__ e_be2,
                 const float* __restrict__ cW1,
                 const float* __restrict__ c_b1, const float* __restrict__ c_g1, const float* __restrict__ c_be1,
                 const float* __restrict__ cW2,
                 float* __restrict__ coord_out, int E) {
    extern __shared__ float smem[];
    int w = threadIdx.x >> 5, l = threadIdx.x & 31;
    float* sw   = smem + w * TILE_F;
    float* meta = smem + 4 * TILE_F + w * META_F;
    int*   srow  = (int*)meta;          // gather-safe row
    int*   svrow = (int*)meta + 16;     // -1 if invalid edge
    int*   scol  = (int*)meta + 32;
    float* scd   = meta + 48;           // 48 floats
    float* srad  = meta + 96;           // 16, 8B aligned
    float* sea   = meta + 112;          // 16

    int base = blockIdx.x * 64 + w * 16;

    if (l < 16) {
        int e = base + l;
        bool v = e < E;
        int ec = v ? e : 0;
        int r, c;
        if (g_idx64) {
            const long long* q = (const long long*)ei;
            r = (int)q[ec]; c = (int)q[(size_t)E + ec];
        } else {
            const int* q = (const int*)ei;
            r = q[ec]; c = q[E + ec];
        }
        float dx = coord[r * 3 + 0] - coord[c * 3 + 0];
        float dy = coord[r * 3 + 1] - coord[c * 3 + 1];
        float dz = coord[r * 3 + 2] - coord[c * 3 + 2];
        float radial = dx * dx + dy * dy + dz * dz;
        float invn = 1.0f / (sqrtf(radial + 1e-8f) + 1.0f);
        srow[l]  = r;
        svrow[l] = v ? r : -1;
        scol[l]  = c;
        scd[l * 3 + 0] = dx * invn;
        scd[l * 3 + 1] = dy * invn;
        scd[l * 3 + 2] = dz * invn;
        srad[l] = radial;
        sea[l]  = eattr[ec];
    }
    __syncwarp();

    u64 acc[8][4];
    init_bias(acc, e_b1, l);

    // ---- layer 1, pass A: h[row] (W1 rows 0..127) ----
#pragma unroll 1
    for (int e = 0; e < 16; e++) {
        int r = srow[e];
#pragma unroll
        for (int m = 0; m < 4; m++) {
            int k = l + 32 * m;
            sw[k * 20 + e] = __ldg(h + (size_t)r * 128 + k);
        }
    }
    __syncwarp();
    gemm_k<128>(sw, eW1, l, acc);
    __syncwarp();

    // ---- layer 1, pass B: h[col] (W1 rows 128..255) ----
#pragma unroll 1
    for (int e = 0; e < 16; e++) {
        int c = scol[e];
#pragma unroll
        for (int m = 0; m < 4; m++) {
            int k = l + 32 * m;
            sw[k * 20 + e] = __ldg(h + (size_t)c * 128 + k);
        }
    }
    __syncwarp();
    gemm_k<128>(sw, eW1 + 128 * 128, l, acc);

    // ---- layer 1, k=256 (radial) and k=257 (edge_attr) ----
    {
        float w6[4], w7[4];
#pragma unroll
        for (int j = 0; j < 4; j++) {
            w6[j] = __ldg(eW1 + 256 * 128 + l + 32 * j);
            w7[j] = __ldg(eW1 + 257 * 128 + l + 32 * j);
        }
#pragma unroll
        for (int p = 0; p < 8; p++) {
            u64 rad2 = *(const u64*)(srad + 2 * p);
            u64 ea2  = *(const u64*)(sea  + 2 * p);
#pragma unroll
            for (int j = 0; j < 4; j++) {
                acc[p][j] = fma2(rad2, pk2(w6[j], w6[j]), acc[p][j]);
                acc[p][j] = fma2(ea2,  pk2(w7[j], w7[j]), acc[p][j]);
            }
        }
    }
    ln_silu(acc, e_g1, e_be1, l);
    __syncwarp();
    store_tile(sw, acc, l);
    __syncwarp();

    // ---- layer 2 -> edge_feat ----
    init_bias(acc, e_b2, l);
    gemm_k<128>(sw, eW2, l, acc);
    ln_silu(acc, e_g2, e_be2, l);

    // scatter edge_feat into agg (coalesced channels per j)
#pragma unroll
    for (int p = 0; p < 8; p++) {
        int r0 = svrow[2 * p], r1 = svrow[2 * p + 1];
#pragma unroll
        for (int j = 0; j < 4; j++) {
            float x0, x1; upk2(acc[p][j], x0, x1);
            int c = l + 32 * j;
            if (r0 >= 0) atomicAdd(&g_agg[(size_t)r0 * 128 + c], x0);
            if (r1 >= 0) atomicAdd(&g_agg[(size_t)r1 * 128 + c], x1);
        }
    }
    __syncwarp();
    store_tile(sw, acc, l);
    __syncwarp();

    // ---- coord MLP ----
    init_bias(acc, c_b1, l);
    gemm_k<128>(sw, cW1, l, acc);
    ln_silu(acc, c_g1, c_be1, l);

    float wv[4];
#pragma unroll
    for (int j = 0; j < 4; j++) wv[j] = __ldg(cW2 + l + 32 * j);
    u64 cms[8];
#pragma unroll
    for (int p = 0; p < 8; p++) {
        u64 s = 0ull;
#pragma unroll
        for (int j = 0; j < 4; j++) s = fma2(acc[p][j], pk2(wv[j], wv[j]), s);
#pragma unroll
        for (int o = 16; o > 0; o >>= 1)
            s = add2(s, __shfl_xor_sync(0xffffffffu, s, o));
        cms[p] = s;
    }
    if (l < 16) {
        float c0, c1; upk2(cms[l >> 1], c0, c1);
        float cmv = (l & 1) ? c1 : c0;
        int r = svrow[l];
        if (r >= 0) {
            atomicAdd(&coord_out[(size_t)r * 3 + 0], scd[l * 3 + 0] * cmv);
            atomicAdd(&coord_out[(size_t)r * 3 + 1], scd[l * 3 + 1] * cmv);
            atomicAdd(&coord_out[(size_t)r * 3 + 2], scd[l * 3 + 2] * cmv);
        }
    }
}

// ---------------- node kernel: 64 nodes / block ----------------
__global__ __launch_bounds__(128, 3)
void node_kernel(const float* __restrict__ h,
                 const float* __restrict__ nW1,
                 const float* __restrict__ n_b1, const float* __restrict__ n_g1,
                 const float* __restrict__ n_be1,
                 const float* __restrict__ nW2, const float* __restrict__ n_b2,
                 float* __restrict__ out, int N) {
    extern __shared__ float smem[];
    int w = threadIdx.x >> 5, l = threadIdx.x & 31;
    float* sw = smem + w * TILE_F;
    int base = blockIdx.x * 64 + w * 16;

    u64 acc[8][4];
    init_bias(acc, n_b1, l);

    // pass A: h (W rows 0..127)
#pragma unroll 1
    for (int e = 0; e < 16; e++) {
        int n = base + e; int nc = (n < N) ? n : 0;
#pragma unroll
        for (int m = 0; m < 4; m++) {
            int k = l + 32 * m;
            sw[k * 20 + e] = __ldg(h + (size_t)nc * 128 + k);
        }
    }
    __syncwarp();
    gemm_k<128>(sw, nW1, l, acc);
    __syncwarp();

    // pass B: agg (W rows 128..255)
#pragma unroll 1
    for (int e = 0; e < 16; e++) {
        int n = base + e; int nc = (n < N) ? n : 0;
#pragma unroll
        for (int m = 0; m < 4; m++) {
            int k = l + 32 * m;
            sw[k * 20 + e] = g_agg[(size_t)nc * 128 + k];
        }
    }
    __syncwarp();
    gemm_k<128>(sw, nW1 + 128 * 128, l, acc);
    ln_silu(acc, n_g1, n_be1, l);
    __syncwarp();
    store_tile(sw, acc, l);
    __syncwarp();

    init_bias(acc, n_b2, l);
    gemm_k<128>(sw, nW2, l, acc);

#pragma unroll
    for (int p = 0; p < 8; p++) {
        int n0 = base + 2 * p, n1 = n0 + 1;
#pragma unroll
        for (int j = 0; j < 4; j++) {
            float x0, x1; upk2(acc[p][j], x0, x1);
            int c = l + 32 * j;
            if (n0 < N) out[(size_t)n0 * 128 + c] = x0 + __ldg(h + (size_t)n0 * 128 + c);
            if (n1 < N) out[(size_t)n1 * 128 + c] = x1 + __ldg(h + (size_t)n1 * 128 + c);
        }
    }
}

// ---------------- launch ----------------
extern "C" void kernel_launch(void* const* d_in, const int* in_sizes, int n_in,
                              void* d_out, int out_size) {
    const float* h     = (const float*)d_in[0];
    const void*  ei    = d_in[1];
    const float* coord = (const float*)d_in[2];
    const float* eattr = (const float*)d_in[3];
    const float* eW1  = (const float*)d_in[4];
    const float* eb1  = (const float*)d_in[5];
    const float* eg1  = (const float*)d_in[6];
    const float* ebe1 = (const float*)d_in[7];
    const float* eW2  = (const float*)d_in[8];
    const float* eb2  = (const float*)d_in[9];
    const float* eg2  = (const float*)d_in[10];
    const float* ebe2 = (const float*)d_in[11];
    const float* nW1  = (const float*)d_in[12];
    const float* nb1  = (const float*)d_in[13];
    const float* ng1  = (const float*)d_in[14];
    const float* nbe1 = (const float*)d_in[15];
    const float* nW2  = (const float*)d_in[16];
    const float* nb2  = (const float*)d_in[17];
    const float* cW1  = (const float*)d_in[18];
    const float* cb1  = (const float*)d_in[19];
    const float* cg1  = (const float*)d_in[20];
    const float* cbe1 = (const float*)d_in[21];
    const float* cW2  = (const float*)d_in[22];

    int N = in_sizes[0] / 128;
    int E = in_sizes[1] / 2;

    float* out       = (float*)d_out;
    float* coord_out = out + (size_t)N * 128;

    cudaFuncSetAttribute(edge_kernel, cudaFuncAttributeMaxDynamicSharedMemorySize, SMEM_B);
    cudaFuncSetAttribute(node_kernel, cudaFuncAttributeMaxDynamicSharedMemorySize, SMEM_B);

    init_kernel<<<(N * 128 + 255) / 256, 256>>>(coord, coord_out, (const unsigned*)ei, N);
    edge_kernel<<<(E + 63) / 64, 128, SMEM_B>>>(h, ei, coord, eattr,
                                                eW1, eb1, eg1, ebe1,
                                                eW2, eb2, eg2, ebe2,
                                                cW1, cb1, cg1, cbe1, cW2,
                                                coord_out, E);
    node_kernel<<<(N + 63) / 64, 128, SMEM_B>>>(h, nW1, nb1, ng1, nbe1, nW2, nb2, out, N);
}

// round 8
// speedup vs baseline: 1.9428x; 1.0008x over previous
#include <cuda_runtime.h>
#include <math.h>

typedef unsigned long long u64;

// ---------------- device scratch (no allocations allowed) ----------------
__device__ float g_agg[25000 * 128]; // segment-sum of edge_feat
__device__ int   g_idx64;            // 1 if edge_index is int64

// ---------------- packed f32x2 helpers ----------------
__device__ __forceinline__ u64 pk2(float lo, float hi) {
    u64 r; asm("mov.b64 %0,{%1,%2};" : "=l"(r) : "f"(lo), "f"(hi)); return r;
}
__device__ __forceinline__ void upk2(u64 v, float& lo, float& hi) {
    asm("mov.b64 {%0,%1},%2;" : "=f"(lo), "=f"(hi) : "l"(v));
}
__device__ __forceinline__ u64 fma2(u64 a, u64 b, u64 c) {
    u64 d; asm("fma.rn.f32x2 %0,%1,%2,%3;" : "=l"(d) : "l"(a), "l"(b), "l"(c)); return d;
}
__device__ __forceinline__ u64 add2(u64 a, u64 b) {
    u64 d; asm("add.rn.f32x2 %0,%1,%2;" : "=l"(d) : "l"(a), "l"(b)); return d;
}
__device__ __forceinline__ u64 mul2(u64 a, u64 b) {
    u64 d; asm("mul.rn.f32x2 %0,%1,%2;" : "=l"(d) : "l"(a), "l"(b)); return d;
}

// ---------------- init: idx detect, zero agg, seed coord_out ----------------
__global__ void init_kernel(const float* __restrict__ coord, float* __restrict__ coord_out,
                            const unsigned* __restrict__ ei, int N) {
    int i = blockIdx.x * blockDim.x + threadIdx.x;
    if (i == 0) {
        int f = 1;
        for (int t = 0; t < 64; t++) if (ei[2 * t + 1] != 0u) { f = 0; break; }
        g_idx64 = f;
    }
    if (i < N * 128) g_agg[i] = 0.0f;
    if (i < N * 3)   coord_out[i] = coord[i];
}

// ============ core warp-level GEMM: 16 edges (8 f32x2 pairs) x 128 ch ============
// sw tile: row k (stride 20 floats), cols 0..15 = edges (pairs adjacent).
// W row-major [K][128]; lane l owns channels l, l+32, l+64, l+96 (coalesced LDG).
template <int K>
__device__ __forceinline__ void gemm_k(const float* __restrict__ sw,
                                       const float* __restrict__ W,
                                       int l, u64 acc[8][4]) {
    const float* wb = W + l;
#pragma unroll 4
    for (int k = 0; k < K; k++) {
        const float* wr = wb + k * 128;
        float f0 = __ldg(wr);
        float f1 = __ldg(wr + 32);
        float f2 = __ldg(wr + 64);
        float f3 = __ldg(wr + 96);
        const float4* a = (const float4*)(sw + k * 20);
        float4 A0 = a[0], A1 = a[1], A2 = a[2], A3 = a[3];
        u64 x[8];
        x[0] = ((const u64*)&A0)[0]; x[1] = ((const u64*)&A0)[1];
        x[2] = ((const u64*)&A1)[0]; x[3] = ((const u64*)&A1)[1];
        x[4] = ((const u64*)&A2)[0]; x[5] = ((const u64*)&A2)[1];
        x[6] = ((const u64*)&A3)[0]; x[7] = ((const u64*)&A3)[1];
        u64 w0 = pk2(f0, f0), w1 = pk2(f1, f1), w2 = pk2(f2, f2), w3 = pk2(f3, f3);
#pragma unroll
        for (int p = 0; p < 8; p++) {
            acc[p][0] = fma2(x[p], w0, acc[p][0]);
            acc[p][1] = fma2(x[p], w1, acc[p][1]);
            acc[p][2] = fma2(x[p], w2, acc[p][2]);
            acc[p][3] = fma2(x[p], w3, acc[p][3]);
        }
    }
}

__device__ __forceinline__ void init_bias(u64 acc[8][4], const float* __restrict__ b, int l) {
#pragma unroll
    for (int j = 0; j < 4; j++) {
        float bb = __ldg(b + l + 32 * j);
        u64 v = pk2(bb, bb);
#pragma unroll
        for (int p = 0; p < 8; p++) acc[p][j] = v;
    }
}

__device__ __forceinline__ void ln_silu(u64 acc[8][4],
                                        const float* __restrict__ g,
                                        const float* __restrict__ be, int l) {
    float gv[4], bv[4];
#pragma unroll
    for (int j = 0; j < 4; j++) { gv[j] = __ldg(g + l + 32 * j); bv[j] = __ldg(be + l + 32 * j); }
#pragma unroll
    for (int p = 0; p < 8; p++) {
        u64 s1 = add2(add2(acc[p][0], acc[p][1]), add2(acc[p][2], acc[p][3]));
        u64 s2 = mul2(acc[p][0], acc[p][0]);
        s2 = fma2(acc[p][1], acc[p][1], s2);
        s2 = fma2(acc[p][2], acc[p][2], s2);
        s2 = fma2(acc[p][3], acc[p][3], s2);
#pragma unroll
        for (int o = 16; o > 0; o >>= 1) {
            s1 = add2(s1, __shfl_xor_sync(0xffffffffu, s1, o));
            s2 = add2(s2, __shfl_xor_sync(0xffffffffu, s2, o));
        }
        float m0, m1, q0, q1;
        upk2(s1, m0, m1); upk2(s2, q0, q1);
        const float inv = 1.0f / 128.0f;
        m0 *= inv; m1 *= inv;
        float v0 = q0 * inv - m0 * m0, v1 = q1 * inv - m1 * m1;
        float r0 = rsqrtf(v0 + 1e-5f), r1 = rsqrtf(v1 + 1e-5f);
#pragma unroll
        for (int j = 0; j < 4; j++) {
            float x0, x1; upk2(acc[p][j], x0, x1);
            x0 = (x0 - m0) * r0 * gv[j] + bv[j];
            x1 = (x1 - m1) * r1 * gv[j] + bv[j];
            x0 = x0 / (1.0f + __expf(-x0));
            x1 = x1 / (1.0f + __expf(-x1));
            acc[p][j] = pk2(x0, x1);
        }
    }
}

__device__ __forceinline__ void store_tile(float* __restrict__ sw, u64 acc[8][4], int l) {
#pragma unroll
    for (int j = 0; j < 4; j++) {
        int c = l + 32 * j;
        u64* d = (u64*)(sw + c * 20);
#pragma unroll
        for (int p = 0; p < 8; p++) d[p] = acc[p][j];
    }
}

// per-warp smem: tile 132 rows x 20 floats = 2640 floats; meta 128 floats
static const int TILE_F  = 2640;
static const int META_F  = 128;
static const int SMEM_B  = (4 * TILE_F + 4 * META_F) * 4;  // 44288 bytes

// ---------------- edge kernel: 64 edges / block, 4 warps x 16 edges ----------------
__global__ __launch_bounds__(128, 3)
void edge_kernel(const float* __restrict__ h, const void* __restrict__ ei,
                 const float* __restrict__ coord, const float* __restrict__ eattr,
                 const float* __restrict__ eW1,
                 const float* __restrict__ e_b1, const float* __restrict__ e_g1, const float* __restrict__ e_be1,
                 const float* __restrict__ eW2,
                 const float* __restrict__ e_b2, const float* __restrict__ e_g2, const float* __restrict__ e_be2,
                 const float* __restrict__ cW1,
                 const float* __restrict__ c_b1, const float* __restrict__ c_g1, const float* __restrict__ c_be1,
                 const float* __restrict__ cW2,
                 float* __restrict__ coord_out, int E) {
    extern __shared__ float smem[];
    int w = threadIdx.x >> 5, l = threadIdx.x & 31;
    float* sw   = smem + w * TILE_F;
    float* meta = smem + 4 * TILE_F + w * META_F;
    int*   srow  = (int*)meta;          // gather-safe row
    int*   svrow = (int*)meta + 16;     // -1 if invalid edge
    int*   scol  = (int*)meta + 32;
    float* scd   = meta + 48;           // 48 floats
    float* srad  = meta + 96;           // 16, 8B aligned
    float* sea   = meta + 112;          // 16

    int base = blockIdx.x * 64 + w * 16;

    if (l < 16) {
        int e = base + l;
        bool v = e < E;
        int ec = v ? e : 0;
        int r, c;
        if (g_idx64) {
            const long long* q = (const long long*)ei;
            r = (int)q[ec]; c = (int)q[(size_t)E + ec];
        } else {
            const int* q = (const int*)ei;
            r = q[ec]; c = q[E + ec];
        }
        float dx = coord[r * 3 + 0] - coord[c * 3 + 0];
        float dy = coord[r * 3 + 1] - coord[c * 3 + 1];
        float dz = coord[r * 3 + 2] - coord[c * 3 + 2];
        float radial = dx * dx + dy * dy + dz * dz;
        float invn = 1.0f / (sqrtf(radial + 1e-8f) + 1.0f);
        srow[l]  = r;
        svrow[l] = v ? r : -1;
        scol[l]  = c;
        scd[l * 3 + 0] = dx * invn;
        scd[l * 3 + 1] = dy * invn;
        scd[l * 3 + 2] = dz * invn;
        srad[l] = radial;
        sea[l]  = eattr[ec];
    }
    __syncwarp();

    u64 acc[8][4];
    init_bias(acc, e_b1, l);

    // ---- layer 1, pass A: h[row] (W1 rows 0..127) ----
#pragma unroll 1
    for (int e = 0; e < 16; e++) {
        int r = srow[e];
#pragma unroll
        for (int m = 0; m < 4; m++) {
            int k = l + 32 * m;
            sw[k * 20 + e] = __ldg(h + (size_t)r * 128 + k);
        }
    }
    __syncwarp();
    gemm_k<128>(sw, eW1, l, acc);
    __syncwarp();

    // ---- layer 1, pass B: h[col] (W1 rows 128..255) ----
#pragma unroll 1
    for (int e = 0; e < 16; e++) {
        int c = scol[e];
#pragma unroll
        for (int m = 0; m < 4; m++) {
            int k = l + 32 * m;
            sw[k * 20 + e] = __ldg(h + (size_t)c * 128 + k);
        }
    }
    __syncwarp();
    gemm_k<128>(sw, eW1 + 128 * 128, l, acc);

    // ---- layer 1, k=256 (radial) and k=257 (edge_attr) ----
    {
        float w6[4], w7[4];
#pragma unroll
        for (int j = 0; j < 4; j++) {
            w6[j] = __ldg(eW1 + 256 * 128 + l + 32 * j);
            w7[j] = __ldg(eW1 + 257 * 128 + l + 32 * j);
        }
#pragma unroll
        for (int p = 0; p < 8; p++) {
            u64 rad2 = *(const u64*)(srad + 2 * p);
            u64 ea2  = *(const u64*)(sea  + 2 * p);
#pragma unroll
            for (int j = 0; j < 4; j++) {
                acc[p][j] = fma2(rad2, pk2(w6[j], w6[j]), acc[p][j]);
                acc[p][j] = fma2(ea2,  pk2(w7[j], w7[j]), acc[p][j]);
            }
        }
    }
    ln_silu(acc, e_g1, e_be1, l);
    __syncwarp();
    store_tile(sw, acc, l);
    __syncwarp();

    // ---- layer 2 -> edge_feat ----
    init_bias(acc, e_b2, l);
    gemm_k<128>(sw, eW2, l, acc);
    ln_silu(acc, e_g2, e_be2, l);

    // scatter edge_feat into agg (coalesced channels per j)
#pragma unroll
    for (int p = 0; p < 8; p++) {
        int r0 = svrow[2 * p], r1 = svrow[2 * p + 1];
#pragma unroll
        for (int j = 0; j < 4; j++) {
            float x0, x1; upk2(acc[p][j], x0, x1);
            int c = l + 32 * j;
            if (r0 >= 0) atomicAdd(&g_agg[(size_t)r0 * 128 + c], x0);
            if (r1 >= 0) atomicAdd(&g_agg[(size_t)r1 * 128 + c], x1);
        }
    }
    __syncwarp();
    store_tile(sw, acc, l);
    __syncwarp();

    // ---- coord MLP ----
    init_bias(acc, c_b1, l);
    gemm_k<128>(sw, cW1, l, acc);
    ln_silu(acc, c_g1, c_be1, l);

    float wv[4];
#pragma unroll
    for (int j = 0; j < 4; j++) wv[j] = __ldg(cW2 + l + 32 * j);
    u64 cms[8];
#pragma unroll
    for (int p = 0; p < 8; p++) {
        u64 s = 0ull;
#pragma unroll
        for (int j = 0; j < 4; j++) s = fma2(acc[p][j], pk2(wv[j], wv[j]), s);
#pragma unroll
        for (int o = 16; o > 0; o >>= 1)
            s = add2(s, __shfl_xor_sync(0xffffffffu, s, o));
        cms[p] = s;
    }
    if (l < 16) {
        float c0, c1; upk2(cms[l >> 1], c0, c1);
        float cmv = (l & 1) ? c1 : c0;
        int r = svrow[l];
        if (r >= 0) {
            atomicAdd(&coord_out[(size_t)r * 3 + 0], scd[l * 3 + 0] * cmv);
            atomicAdd(&coord_out[(size_t)r * 3 + 1], scd[l * 3 + 1] * cmv);
            atomicAdd(&coord_out[(size_t)r * 3 + 2], scd[l * 3 + 2] * cmv);
        }
    }
}

// ---------------- node kernel: 64 nodes / block ----------------
__global__ __launch_bounds__(128, 3)
void node_kernel(const float* __restrict__ h,
                 const float* __restrict__ nW1,
                 const float* __restrict__ n_b1, const float* __restrict__ n_g1,
                 const float* __restrict__ n_be1,
                 const float* __restrict__ nW2, const float* __restrict__ n_b2,
                 float* __restrict__ out, int N) {
    extern __shared__ float smem[];
    int w = threadIdx.x >> 5, l = threadIdx.x & 31;
    float* sw = smem + w * TILE_F;
    int base = blockIdx.x * 64 + w * 16;

    u64 acc[8][4];
    init_bias(acc, n_b1, l);

    // pass A: h (W rows 0..127)
#pragma unroll 1
    for (int e = 0; e < 16; e++) {
        int n = base + e; int nc = (n < N) ? n : 0;
#pragma unroll
        for (int m = 0; m < 4; m++) {
            int k = l + 32 * m;
            sw[k * 20 + e] = __ldg(h + (size_t)nc * 128 + k);
        }
    }
    __syncwarp();
    gemm_k<128>(sw, nW1, l, acc);
    __syncwarp();

    // pass B: agg (W rows 128..255)
#pragma unroll 1
    for (int e = 0; e < 16; e++) {
        int n = base + e; int nc = (n < N) ? n : 0;
#pragma unroll
        for (int m = 0; m < 4; m++) {
            int k = l + 32 * m;
            sw[k * 20 + e] = g_agg[(size_t)nc * 128 + k];
        }
    }
    __syncwarp();
    gemm_k<128>(sw, nW1 + 128 * 128, l, acc);
    ln_silu(acc, n_g1, n_be1, l);
    __syncwarp();
    store_tile(sw, acc, l);
    __syncwarp();

    init_bias(acc, n_b2, l);
    gemm_k<128>(sw, nW2, l, acc);

#pragma unroll
    for (int p = 0; p < 8; p++) {
        int n0 = base + 2 * p, n1 = n0 + 1;
#pragma unroll
        for (int j = 0; j < 4; j++) {
            float x0, x1; upk2(acc[p][j], x0, x1);
            int c = l + 32 * j;
            if (n0 < N) out[(size_t)n0 * 128 + c] = x0 + __ldg(h + (size_t)n0 * 128 + c);
            if (n1 < N) out[(size_t)n1 * 128 + c] = x1 + __ldg(h + (size_t)n1 * 128 + c);
        }
    }
}

// ---------------- launch ----------------
extern "C" void kernel_launch(void* const* d_in, const int* in_sizes, int n_in,
                              void* d_out, int out_size) {
    const float* h     = (const float*)d_in[0];
    const void*  ei    = d_in[1];
    const float* coord = (const float*)d_in[2];
    const float* eattr = (const float*)d_in[3];
    const float* eW1  = (const float*)d_in[4];
    const float* eb1  = (const float*)d_in[5];
    const float* eg1  = (const float*)d_in[6];
    const float* ebe1 = (const float*)d_in[7];
    const float* eW2  = (const float*)d_in[8];
    const float* eb2  = (const float*)d_in[9];
    const float* eg2  = (const float*)d_in[10];
    const float* ebe2 = (const float*)d_in[11];
    const float* nW1  = (const float*)d_in[12];
    const float* nb1  = (const float*)d_in[13];
    const float* ng1  = (const float*)d_in[14];
    const float* nbe1 = (const float*)d_in[15];
    const float* nW2  = (const float*)d_in[16];
    const float* nb2  = (const float*)d_in[17];
    const float* cW1  = (const float*)d_in[18];
    const float* cb1  = (const float*)d_in[19];
    const float* cg1  = (const float*)d_in[20];
    const float* cbe1 = (const float*)d_in[21];
    const float* cW2  = (const float*)d_in[22];

    int N = in_sizes[0] / 128;
    int E = in_sizes[1] / 2;

    float* out       = (float*)d_out;
    float* coord_out = out + (size_t)N * 128;

    cudaFuncSetAttribute(edge_kernel, cudaFuncAttributeMaxDynamicSharedMemorySize, SMEM_B);
    cudaFuncSetAttribute(node_kernel, cudaFuncAttributeMaxDynamicSharedMemorySize, SMEM_B);

    init_kernel<<<(N * 128 + 255) / 256, 256>>>(coord, coord_out, (const unsigned*)ei, N);
    edge_kernel<<<(E + 63) / 64, 128, SMEM_B>>>(h, ei, coord, eattr,
                                                eW1, eb1, eg1, ebe1,
                                                eW2, eb2, eg2, ebe2,
                                                cW1, cb1, cg1, cbe1, cW2,
                                                coord_out, E);
    node_kernel<<<(N + 63) / 64, 128, SMEM_B>>>(h, nW1, nb1, ng1, nbe1, nW2, nb2, out, N);
}

// round 12
// speedup vs baseline: 3.5759x; 1.8406x over previous
#include <cuda_runtime.h>
#include <math.h>

typedef unsigned long long u64;

// ---------------- device scratch (no allocations allowed) ----------------
__device__ float g_agg[25000 * 128]; // segment-sum of edge_feat
__device__ float g_P1 [25000 * 128]; // h @ e_W1[0:128] + e_b1
__device__ float g_P2 [25000 * 128]; // h @ e_W1[128:256]
__device__ int   g_idx64;            // 1 if edge_index is int64

// ---------------- packed f32x2 helpers ----------------
__device__ __forceinline__ u64 pk2(float lo, float hi) {
    u64 r; asm("mov.b64 %0,{%1,%2};" : "=l"(r) : "f"(lo), "f"(hi)); return r;
}
__device__ __forceinline__ void upk2(u64 v, float& lo, float& hi) {
    asm("mov.b64 {%0,%1},%2;" : "=f"(lo), "=f"(hi) : "l"(v));
}
__device__ __forceinline__ u64 fma2(u64 a, u64 b, u64 c) {
    u64 d; asm("fma.rn.f32x2 %0,%1,%2,%3;" : "=l"(d) : "l"(a), "l"(b), "l"(c)); return d;
}
__device__ __forceinline__ u64 add2(u64 a, u64 b) {
    u64 d; asm("add.rn.f32x2 %0,%1,%2;" : "=l"(d) : "l"(a), "l"(b)); return d;
}
__device__ __forceinline__ u64 mul2(u64 a, u64 b) {
    u64 d; asm("mul.rn.f32x2 %0,%1,%2;" : "=l"(d) : "l"(a), "l"(b)); return d;
}

// ---------------- init: idx detect, zero agg, seed coord_out ----------------
__global__ void init_kernel(const float* __restrict__ coord, float* __restrict__ coord_out,
                            const unsigned* __restrict__ ei, int N) {
    int i = blockIdx.x * blockDim.x + threadIdx.x;
    if (i == 0) {
        int f = 1;
        for (int t = 0; t < 64; t++) if (ei[2 * t + 1] != 0u) { f = 0; break; }
        g_idx64 = f;
    }
    if (i < N * 128) g_agg[i] = 0.0f;
    if (i < N * 3)   coord_out[i] = coord[i];
}

// ============ core warp-level GEMM: 16 rows (8 f32x2 pairs) x 128 ch ============
// sw tile: row k (stride 20 floats), cols 0..15 = rows (pairs adjacent).
// W row-major [K][128]; lane l owns channels l, l+32, l+64, l+96 (coalesced LDG).
template <int K>
__device__ __forceinline__ void gemm_k(const float* __restrict__ sw,
                                       const float* __restrict__ W,
                                       int l, u64 acc[8][4]) {
    const float* wb = W + l;
#pragma unroll 4
    for (int k = 0; k < K; k++) {
        const float* wr = wb + k * 128;
        float f0 = __ldg(wr);
        float f1 = __ldg(wr + 32);
        float f2 = __ldg(wr + 64);
        float f3 = __ldg(wr + 96);
        const float4* a = (const float4*)(sw + k * 20);
        float4 A0 = a[0], A1 = a[1], A2 = a[2], A3 = a[3];
        u64 x[8];
        x[0] = ((const u64*)&A0)[0]; x[1] = ((const u64*)&A0)[1];
        x[2] = ((const u64*)&A1)[0]; x[3] = ((const u64*)&A1)[1];
        x[4] = ((const u64*)&A2)[0]; x[5] = ((const u64*)&A2)[1];
        x[6] = ((const u64*)&A3)[0]; x[7] = ((const u64*)&A3)[1];
        u64 w0 = pk2(f0, f0), w1 = pk2(f1, f1), w2 = pk2(f2, f2), w3 = pk2(f3, f3);
#pragma unroll
        for (int p = 0; p < 8; p++) {
            acc[p][0] = fma2(x[p], w0, acc[p][0]);
            acc[p][1] = fma2(x[p], w1, acc[p][1]);
            acc[p][2] = fma2(x[p], w2, acc[p][2]);
            acc[p][3] = fma2(x[p], w3, acc[p][3]);
        }
    }
}

__device__ __forceinline__ void init_bias(u64 acc[8][4], const float* __restrict__ b, int l) {
#pragma unroll
    for (int j = 0; j < 4; j++) {
        float bb = __ldg(b + l + 32 * j);
        u64 v = pk2(bb, bb);
#pragma unroll
        for (int p = 0; p < 8; p++) acc[p][j] = v;
    }
}

__device__ __forceinline__ void init_zero(u64 acc[8][4]) {
#pragma unroll
    for (int j = 0; j < 4; j++)
#pragma unroll
        for (int p = 0; p < 8; p++) acc[p][j] = 0ull;
}

__device__ __forceinline__ void ln_silu(u64 acc[8][4],
                                        const float* __restrict__ g,
                                        const float* __restrict__ be, int l) {
    float gv[4], bv[4];
#pragma unroll
    for (int j = 0; j < 4; j++) { gv[j] = __ldg(g + l + 32 * j); bv[j] = __ldg(be + l + 32 * j); }
#pragma unroll
    for (int p = 0; p < 8; p++) {
        u64 s1 = add2(add2(acc[p][0], acc[p][1]), add2(acc[p][2], acc[p][3]));
        u64 s2 = mul2(acc[p][0], acc[p][0]);
        s2 = fma2(acc[p][1], acc[p][1], s2);
        s2 = fma2(acc[p][2], acc[p][2], s2);
        s2 = fma2(acc[p][3], acc[p][3], s2);
#pragma unroll
        for (int o = 16; o > 0; o >>= 1) {
            s1 = add2(s1, __shfl_xor_sync(0xffffffffu, s1, o));
            s2 = add2(s2, __shfl_xor_sync(0xffffffffu, s2, o));
        }
        float m0, m1, q0, q1;
        upk2(s1, m0, m1); upk2(s2, q0, q1);
        const float inv = 1.0f / 128.0f;
        m0 *= inv; m1 *= inv;
        float v0 = q0 * inv - m0 * m0, v1 = q1 * inv - m1 * m1;
        float r0 = rsqrtf(v0 + 1e-5f), r1 = rsqrtf(v1 + 1e-5f);
#pragma unroll
        for (int j = 0; j < 4; j++) {
            float x0, x1; upk2(acc[p][j], x0, x1);
            x0 = (x0 - m0) * r0 * gv[j] + bv[j];
            x1 = (x1 - m1) * r1 * gv[j] + bv[j];
            x0 = x0 * __fdividef(1.0f, 1.0f + __expf(-x0));
            x1 = x1 * __fdividef(1.0f, 1.0f + __expf(-x1));
            acc[p][j] = pk2(x0, x1);
        }
    }
}

__device__ __forceinline__ void store_tile(float* __restrict__ sw, u64 acc[8][4], int l) {
#pragma unroll
    for (int j = 0; j < 4; j++) {
        int c = l + 32 * j;
        u64* d = (u64*)(sw + c * 20);
#pragma unroll
        for (int p = 0; p < 8; p++) d[p] = acc[p][j];
    }
}

// per-warp smem: tile 132 rows x 20 floats = 2640 floats; meta 128 floats
static const int TILE_F  = 2640;
static const int META_F  = 128;
static const int SMEM_B  = (4 * TILE_F + 4 * META_F) * 4;  // 44288 bytes

// ---------------- pre kernel: P1 = h@W1a + b1, P2 = h@W1b ----------------
__global__ __launch_bounds__(128, 3)
void pre_kernel(const float* __restrict__ h, const float* __restrict__ eW1,
                const float* __restrict__ e_b1, int N) {
    extern __shared__ float smem[];
    int w = threadIdx.x >> 5, l = threadIdx.x & 31;
    float* sw = smem + w * TILE_F;
    int base = blockIdx.x * 64 + w * 16;

    // gather h tile once
#pragma unroll 1
    for (int e = 0; e < 16; e++) {
        int n = base + e; int nc = (n < N) ? n : 0;
#pragma unroll
        for (int m = 0; m < 4; m++) {
            int k = l + 32 * m;
            sw[k * 20 + e] = __ldg(h + (size_t)nc * 128 + k);
        }
    }
    __syncwarp();

    u64 acc[8][4];

    // P1 = h @ W1[0:128] + b1
    init_bias(acc, e_b1, l);
    gemm_k<128>(sw, eW1, l, acc);
#pragma unroll
    for (int p = 0; p < 8; p++) {
        int n0 = base + 2 * p, n1 = n0 + 1;
#pragma unroll
        for (int j = 0; j < 4; j++) {
            float x0, x1; upk2(acc[p][j], x0, x1);
            int c = l + 32 * j;
            if (n0 < N) g_P1[(size_t)n0 * 128 + c] = x0;
            if (n1 < N) g_P1[(size_t)n1 * 128 + c] = x1;
        }
    }

    // P2 = h @ W1[128:256]
    init_zero(acc);
    gemm_k<128>(sw, eW1 + 128 * 128, l, acc);
#pragma unroll
    for (int p = 0; p < 8; p++) {
        int n0 = base + 2 * p, n1 = n0 + 1;
#pragma unroll
        for (int j = 0; j < 4; j++) {
            float x0, x1; upk2(acc[p][j], x0, x1);
            int c = l + 32 * j;
            if (n0 < N) g_P2[(size_t)n0 * 128 + c] = x0;
            if (n1 < N) g_P2[(size_t)n1 * 128 + c] = x1;
        }
    }
}

// ---------------- edge kernel: 64 edges / block, 4 warps x 16 edges ----------------
__global__ __launch_bounds__(128, 3)
void edge_kernel(const void* __restrict__ ei,
                 const float* __restrict__ coord, const float* __restrict__ eattr,
                 const float* __restrict__ eW1,
                 const float* __restrict__ e_g1, const float* __restrict__ e_be1,
                 const float* __restrict__ eW2,
                 const float* __restrict__ e_b2, const float* __restrict__ e_g2, const float* __restrict__ e_be2,
                 const float* __restrict__ cW1,
                 const float* __restrict__ c_b1, const float* __restrict__ c_g1, const float* __restrict__ c_be1,
                 const float* __restrict__ cW2,
                 float* __restrict__ coord_out, int E) {
    extern __shared__ float smem[];
    int w = threadIdx.x >> 5, l = threadIdx.x & 31;
    float* sw   = smem + w * TILE_F;
    float* meta = smem + 4 * TILE_F + w * META_F;
    int*   srow  = (int*)meta;          // gather-safe row
    int*   svrow = (int*)meta + 16;     // -1 if invalid edge
    int*   scol  = (int*)meta + 32;
    float* scd   = meta + 48;           // 48 floats
    float* srad  = meta + 96;           // 16, 8B aligned
    float* sea   = meta + 112;          // 16

    int base = blockIdx.x * 64 + w * 16;

    if (l < 16) {
        int e = base + l;
        bool v = e < E;
        int ec = v ? e : 0;
        int r, c;
        if (g_idx64) {
            const long long* q = (const long long*)ei;
            r = (int)q[ec]; c = (int)q[(size_t)E + ec];
        } else {
            const int* q = (const int*)ei;
            r = q[ec]; c = q[E + ec];
        }
        float dx = coord[r * 3 + 0] - coord[c * 3 + 0];
        float dy = coord[r * 3 + 1] - coord[c * 3 + 1];
        float dz = coord[r * 3 + 2] - coord[c * 3 + 2];
        float radial = dx * dx + dy * dy + dz * dz;
        float invn = 1.0f / (sqrtf(radial + 1e-8f) + 1.0f);
        srow[l]  = r;
        svrow[l] = v ? r : -1;
        scol[l]  = c;
        scd[l * 3 + 0] = dx * invn;
        scd[l * 3 + 1] = dy * invn;
        scd[l * 3 + 2] = dz * invn;
        srad[l] = radial;
        sea[l]  = eattr[ec];
    }
    __syncwarp();

    u64 acc[8][4];

    // ---- layer 1 DIRECT: P1[row] + P2[col] + radial*W[256] + ea*W[257] ----
    {
        float w6[4], w7[4];
#pragma unroll
        for (int j = 0; j < 4; j++) {
            w6[j] = __ldg(eW1 + 256 * 128 + l + 32 * j);
            w7[j] = __ldg(eW1 + 257 * 128 + l + 32 * j);
        }
#pragma unroll
        for (int p = 0; p < 8; p++) {
            int r0 = srow[2 * p],     r1 = srow[2 * p + 1];
            int c0 = scol[2 * p],     c1 = scol[2 * p + 1];
            const float* p1a = g_P1 + (size_t)r0 * 128 + l;
            const float* p1b = g_P1 + (size_t)r1 * 128 + l;
            const float* p2a = g_P2 + (size_t)c0 * 128 + l;
            const float* p2b = g_P2 + (size_t)c1 * 128 + l;
            u64 rad2 = *(const u64*)(srad + 2 * p);
            u64 ea2  = *(const u64*)(sea  + 2 * p);
#pragma unroll
            for (int j = 0; j < 4; j++) {
                float a0 = __ldg(p1a + 32 * j) + __ldg(p2a + 32 * j);
                float a1 = __ldg(p1b + 32 * j) + __ldg(p2b + 32 * j);
                u64 v = pk2(a0, a1);
                v = fma2(rad2, pk2(w6[j], w6[j]), v);
                v = fma2(ea2,  pk2(w7[j], w7[j]), v);
                acc[p][j] = v;
            }
        }
    }
    ln_silu(acc, e_g1, e_be1, l);
    store_tile(sw, acc, l);
    __syncwarp();

    // ---- layer 2 -> edge_feat ----
    init_bias(acc, e_b2, l);
    gemm_k<128>(sw, eW2, l, acc);
    ln_silu(acc, e_g2, e_be2, l);

    // scatter edge_feat into agg (coalesced channels per j)
#pragma unroll
    for (int p = 0; p < 8; p++) {
        int r0 = svrow[2 * p], r1 = svrow[2 * p + 1];
#pragma unroll
        for (int j = 0; j < 4; j++) {
            float x0, x1; upk2(acc[p][j], x0, x1);
            int c = l + 32 * j;
            if (r0 >= 0) atomicAdd(&g_agg[(size_t)r0 * 128 + c], x0);
            if (r1 >= 0) atomicAdd(&g_agg[(size_t)r1 * 128 + c], x1);
        }
    }
    __syncwarp();
    store_tile(sw, acc, l);
    __syncwarp();

    // ---- coord MLP ----
    init_bias(acc, c_b1, l);
    gemm_k<128>(sw, cW1, l, acc);
    ln_silu(acc, c_g1, c_be1, l);

    float wv[4];
#pragma unroll
    for (int j = 0; j < 4; j++) wv[j] = __ldg(cW2 + l + 32 * j);
    u64 cms[8];
#pragma unroll
    for (int p = 0; p < 8; p++) {
        u64 s = 0ull;
#pragma unroll
        for (int j = 0; j < 4; j++) s = fma2(acc[p][j], pk2(wv[j], wv[j]), s);
#pragma unroll
        for (int o = 16; o > 0; o >>= 1)
            s = add2(s, __shfl_xor_sync(0xffffffffu, s, o));
        cms[p] = s;
    }
    if (l < 16) {
        float c0, c1; upk2(cms[l >> 1], c0, c1);
        float cmv = (l & 1) ? c1 : c0;
        int r = svrow[l];
        if (r >= 0) {
            atomicAdd(&coord_out[(size_t)r * 3 + 0], scd[l * 3 + 0] * cmv);
            atomicAdd(&coord_out[(size_t)r * 3 + 1], scd[l * 3 + 1] * cmv);
            atomicAdd(&coord_out[(size_t)r * 3 + 2], scd[l * 3 + 2] * cmv);
        }
    }
}

// ---------------- node kernel: 64 nodes / block ----------------
__global__ __launch_bounds__(128, 3)
void node_kernel(const float* __restrict__ h,
                 const float* __restrict__ nW1,
                 const float* __restrict__ n_b1, const float* __restrict__ n_g1,
                 const float* __restrict__ n_be1,
                 const float* __restrict__ nW2, const float* __restrict__ n_b2,
                 float* __restrict__ out, int N) {
    extern __shared__ float smem[];
    int w = threadIdx.x >> 5, l = threadIdx.x & 31;
    float* sw = smem + w * TILE_F;
    int base = blockIdx.x * 64 + w * 16;

    u64 acc[8][4];
    init_bias(acc, n_b1, l);

    // pass A: h (W rows 0..127)
#pragma unroll 1
    for (int e = 0; e < 16; e++) {
        int n = base + e; int nc = (n < N) ? n : 0;
#pragma unroll
        for (int m = 0; m < 4; m++) {
            int k = l + 32 * m;
            sw[k * 20 + e] = __ldg(h + (size_t)nc * 128 + k);
        }
    }
    __syncwarp();
    gemm_k<128>(sw, nW1, l, acc);
    __syncwarp();

    // pass B: agg (W rows 128..255)
#pragma unroll 1
    for (int e = 0; e < 16; e++) {
        int n = base + e; int nc = (n < N) ? n : 0;
#pragma unroll
        for (int m = 0; m < 4; m++) {
            int k = l + 32 * m;
            sw[k * 20 + e] = g_agg[(size_t)nc * 128 + k];
        }
    }
    __syncwarp();
    gemm_k<128>(sw, nW1 + 128 * 128, l, acc);
    ln_silu(acc, n_g1, n_be1, l);
    __syncwarp();
    store_tile(sw, acc, l);
    __syncwarp();

    init_bias(acc, n_b2, l);
    gemm_k<128>(sw, nW2, l, acc);

#pragma unroll
    for (int p = 0; p < 8; p++) {
        int n0 = base + 2 * p, n1 = n0 + 1;
#pragma unroll
        for (int j = 0; j < 4; j++) {
            float x0, x1; upk2(acc[p][j], x0, x1);
            int c = l + 32 * j;
            if (n0 < N) out[(size_t)n0 * 128 + c] = x0 + __ldg(h + (size_t)n0 * 128 + c);
            if (n1 < N) out[(size_t)n1 * 128 + c] = x1 + __ldg(h + (size_t)n1 * 128 + c);
        }
    }
}

// ---------------- launch ----------------
extern "C" void kernel_launch(void* const* d_in, const int* in_sizes, int n_in,
                              void* d_out, int out_size) {
    const float* h     = (const float*)d_in[0];
    const void*  ei    = d_in[1];
    const float* coord = (const float*)d_in[2];
    const float* eattr = (const float*)d_in[3];
    const float* eW1  = (const float*)d_in[4];
    const float* eb1  = (const float*)d_in[5];
    const float* eg1  = (const float*)d_in[6];
    const float* ebe1 = (const float*)d_in[7];
    const float* eW2  = (const float*)d_in[8];
    const float* eb2  = (const float*)d_in[9];
    const float* eg2  = (const float*)d_in[10];
    const float* ebe2 = (const float*)d_in[11];
    const float* nW1  = (const float*)d_in[12];
    const float* nb1  = (const float*)d_in[13];
    const float* ng1  = (const float*)d_in[14];
    const float* nbe1 = (const float*)d_in[15];
    const float* nW2  = (const float*)d_in[16];
    const float* nb2  = (const float*)d_in[17];
    const float* cW1  = (const float*)d_in[18];
    const float* cb1  = (const float*)d_in[19];
    const float* cg1  = (const float*)d_in[20];
    const float* cbe1 = (const float*)d_in[21];
    const float* cW2  = (const float*)d_in[22];

    int N = in_sizes[0] / 128;
    int E = in_sizes[1] / 2;

    float* out       = (float*)d_out;
    float* coord_out = out + (size_t)N * 128;

    cudaFuncSetAttribute(pre_kernel,  cudaFuncAttributeMaxDynamicSharedMemorySize, SMEM_B);
    cudaFuncSetAttribute(edge_kernel, cudaFuncAttributeMaxDynamicSharedMemorySize, SMEM_B);
    cudaFuncSetAttribute(node_kernel, cudaFuncAttributeMaxDynamicSharedMemorySize, SMEM_B);

    init_kernel<<<(N * 128 + 255) / 256, 256>>>(coord, coord_out, (const unsigned*)ei, N);
    pre_kernel<<<(N + 63) / 64, 128, SMEM_B>>>(h, eW1, eb1, N);
    edge_kernel<<<(E + 63) / 64, 128, SMEM_B>>>(ei, coord, eattr,
                                                eW1, eg1, ebe1,
                                                eW2, eb2, eg2, ebe2,
                                                cW1, cb1, cg1, cbe1, cW2,
                                                coord_out, E);
    node_kernel<<<(N + 63) / 64, 128, SMEM_B>>>(h, nW1, nb1, ng1, nbe1, nW2, nb2, out, N);
}